// round 2
// baseline (speedup 1.0000x reference)
#include <cuda_runtime.h>
#include <cstdint>
#include <math.h>

#define NN   64
#define BB   32
#define EE   4032
#define FF   256
#define BIG_M  (BB*EE)    // 129024
#define NODE_M (BB*NN)    // 2048
#define BIG_CH  (BIG_M/64)   // 2016
#define NODE_CH (NODE_M/64)  // 32

// ---------------- scratch (device globals; no allocs) ----------------
__device__ float g_nodeA[NODE_M*FF];
__device__ float g_nodeB[NODE_M*FF];
__device__ float g_nodeC[NODE_M*FF];
__device__ float g_nodeD[NODE_M*FF];
__device__ float g_P[NODE_M*FF];
__device__ float g_Q[NODE_M*FF];
__device__ float g_S[NODE_M*FF];
__device__ float g_R[NODE_M*FF];
__device__ float g_inc[NODE_M*FF];
__device__ float g_bigA[(size_t)BIG_M*FF];
__device__ float g_bigB[(size_t)BIG_M*FF];
__device__ float g_psum[BIG_CH*FF];
__device__ float g_psq[BIG_CH*FF];
__device__ float g_scale[4*FF];
__device__ float g_shift[4*FF];
__device__ float g_wskip[FF*FF];
__device__ float g_dbias[FF];
__device__ float g_fcw2[2*FF];
__device__ float g_fcb2[2];

__device__ __forceinline__ float eluf(float x){ return x > 0.f ? x : expm1f(x); }

// ---------------- generic 64x64-tile GEMM over K=256 ----------------
// MA=0: A is a direct [M,256] matrix (optional per-feature input affine AFF)
// MA=1: A[r][k] = ELU(P[send(r)]+Q[recv(r)]) (node->edge gather, bias folded in P)
// SR  : epilogue adds S[send(r)][c] + R[recv(r)][c] + dbias[c] before activation
// STATS: write per-(rowblock,col) partial sum/sumsq (deterministic, no atomics)
template<int MA, bool AFF, bool BIAS, bool ELUF, bool STATS, bool SR>
__global__ __launch_bounds__(64) void gemm_k(
    const float* __restrict__ A, const float* __restrict__ P, const float* __restrict__ Q,
    const float* __restrict__ W, const float* __restrict__ bias,
    const float* __restrict__ aSc, const float* __restrict__ aSh,
    const float* __restrict__ Sg, const float* __restrict__ Rg, const float* __restrict__ db,
    float* __restrict__ C, float* __restrict__ pSum, float* __restrict__ pSq)
{
    __shared__ __align__(16) float As[16][68];
    __shared__ __align__(16) float Bs[16][68];
    __shared__ int sPO[64], sQO[64];
    __shared__ float rS[64][8], rQ2[64][8];

    const int tid = threadIdx.x;
    const int rowbase = blockIdx.x * 64;
    const int n0 = blockIdx.y * 64;

    if (MA==1 || SR) {
        if (tid < 64) {
            int gr  = rowbase + tid;
            int b   = gr / EE;
            int e   = gr - b*EE;
            int snd = e / 63;
            int jp  = e - snd*63;
            int rcv = jp + (jp >= snd ? 1 : 0);
            sPO[tid] = (b*NN + snd)*FF;
            sQO[tid] = (b*NN + rcv)*FF;
        }
        __syncthreads();
    }

    const int ty = tid >> 3, tx = tid & 7;
    float acc[8][8];
    #pragma unroll
    for (int i=0;i<8;i++)
        #pragma unroll
        for (int j=0;j<8;j++) acc[i][j]=0.f;

    for (int k0 = 0; k0 < FF; k0 += 16) {
        // A tile: 64 rows x 16 k, transposed into As[k][m]
        #pragma unroll
        for (int p=0;p<4;p++){
            int idx = p*64 + tid;
            int row = idx >> 2, kq = idx & 3;
            float4 v;
            if (MA==0){
                v = *(const float4*)(A + (size_t)(rowbase+row)*FF + k0 + kq*4);
                if (AFF){
                    const float4 sc = *(const float4*)(aSc + k0 + kq*4);
                    const float4 sh = *(const float4*)(aSh + k0 + kq*4);
                    v.x = fmaf(sc.x, v.x, sh.x);
                    v.y = fmaf(sc.y, v.y, sh.y);
                    v.z = fmaf(sc.z, v.z, sh.z);
                    v.w = fmaf(sc.w, v.w, sh.w);
                }
            } else {
                float4 a4 = *(const float4*)(P + sPO[row] + k0 + kq*4);
                float4 b4 = *(const float4*)(Q + sQO[row] + k0 + kq*4);
                v.x = eluf(a4.x + b4.x);
                v.y = eluf(a4.y + b4.y);
                v.z = eluf(a4.z + b4.z);
                v.w = eluf(a4.w + b4.w);
            }
            As[kq*4+0][row]=v.x; As[kq*4+1][row]=v.y;
            As[kq*4+2][row]=v.z; As[kq*4+3][row]=v.w;
        }
        // B tile: 16 k x 64 n
        #pragma unroll
        for (int p=0;p<4;p++){
            int idx = p*64 + tid;
            int kk = idx >> 4, nq = idx & 15;
            *(float4*)&Bs[kk][nq*4] = *(const float4*)(W + (size_t)(k0+kk)*FF + n0 + nq*4);
        }
        __syncthreads();
        #pragma unroll
        for (int k=0;k<16;k++){
            float a0[8], b0[8];
            *(float4*)&a0[0] = *(float4*)&As[k][ty*8];
            *(float4*)&a0[4] = *(float4*)&As[k][ty*8+4];
            *(float4*)&b0[0] = *(float4*)&Bs[k][tx*8];
            *(float4*)&b0[4] = *(float4*)&Bs[k][tx*8+4];
            #pragma unroll
            for (int i=0;i<8;i++)
                #pragma unroll
                for (int j=0;j<8;j++)
                    acc[i][j] = fmaf(a0[i], b0[j], acc[i][j]);
        }
        __syncthreads();
    }

    // epilogue
    #pragma unroll
    for (int i=0;i<8;i++){
        int lrow = ty*8+i;
        int grow = rowbase + lrow;
        #pragma unroll
        for (int j=0;j<8;j++){
            int col = n0 + tx*8 + j;
            float v = acc[i][j];
            if (BIAS) v += bias[col];
            if (SR)   v += Sg[sPO[lrow] + col] + Rg[sQO[lrow] + col] + db[col];
            if (ELUF) v = eluf(v);
            acc[i][j] = v;
        }
        float* cp = C + (size_t)grow*FF + n0 + tx*8;
        *(float4*)cp     = make_float4(acc[i][0],acc[i][1],acc[i][2],acc[i][3]);
        *(float4*)(cp+4) = make_float4(acc[i][4],acc[i][5],acc[i][6],acc[i][7]);
    }

    if (STATS){
        #pragma unroll
        for (int j=0;j<8;j++){
            float s=0.f,q=0.f;
            #pragma unroll
            for (int i=0;i<8;i++){ float v=acc[i][j]; s+=v; q=fmaf(v,v,q); }
            rS[tid][j]=s; rQ2[tid][j]=q;
        }
        __syncthreads();
        if (tid < 64){
            int ctx = tid>>3, cj = tid&7;
            float s=0.f,q=0.f;
            #pragma unroll
            for (int t=0;t<8;t++){ s += rS[t*8+ctx][cj]; q += rQ2[t*8+ctx][cj]; }
            pSum[(size_t)blockIdx.x*FF + n0 + tid] = s;
            pSq [(size_t)blockIdx.x*FF + n0 + tid] = q;
        }
    }
}

// ---------------- small kernels ----------------
__global__ void finalize_bn(const float* __restrict__ pSum, const float* __restrict__ pSq,
                            int nchunks, const float* __restrict__ g, const float* __restrict__ beta,
                            float invM, float* __restrict__ sc, float* __restrict__ sh)
{
    int f = threadIdx.x;
    float s=0.f,q=0.f;
    for (int c=0;c<nchunks;c++){ s += pSum[(size_t)c*FF+f]; q += pSq[(size_t)c*FF+f]; }
    float mean = s*invM;
    float var  = fmaf(-mean, mean, q*invM);
    float a = g[f]*rsqrtf(var + 1e-5f);
    sc[f]=a; sh[f] = fmaf(-mean, a, beta[f]);
}

__global__ void edge2node_k(const float* __restrict__ h2, const float* __restrict__ sc,
                            const float* __restrict__ sh, float* __restrict__ inc)
{
    int bn = blockIdx.x; int b = bn >> 6; int n = bn & 63; int f = threadIdx.x;
    const float* base = h2 + (size_t)b*EE*FF + f;
    float s = 0.f;
    #pragma unroll
    for (int j=0;j<NN;j++){
        if (j==n) continue;
        int e = j*63 + (j < n ? n-1 : n);
        s += base[(size_t)e*FF];
    }
    inc[(size_t)bn*FF+f] = (sc[f]*s + 63.f*sh[f]) * (1.f/64.f);
}

__global__ void fold_skip_k(const float* __restrict__ w1, const float* __restrict__ sc2,
                            float* __restrict__ wsk)
{
    int f = blockIdx.x, c = threadIdx.x;
    wsk[f*FF+c] = sc2[f]*w1[(512+f)*FF + c];
}

__global__ void fold_dbias_k(const float* __restrict__ w1, const float* __restrict__ b1,
                             const float* __restrict__ sh2, float* __restrict__ db)
{
    int c = threadIdx.x;
    float s = b1[c];
    for (int f=0; f<FF; f++) s = fmaf(sh2[f], w1[(512+f)*FF + c], s);
    db[c]=s;
}

__global__ void fold_fc_k(const float* __restrict__ fcw, const float* __restrict__ fcb,
                          const float* __restrict__ sc, const float* __restrict__ sh,
                          float* __restrict__ fcw2, float* __restrict__ fcb2)
{
    int t = threadIdx.x;
    fcw2[2*t]   = sc[t]*fcw[2*t];
    fcw2[2*t+1] = sc[t]*fcw[2*t+1];
    if (t < 2){
        float s = fcb[t];
        for (int f=0; f<FF; f++) s = fmaf(sh[f], fcw[2*f+t], s);
        fcb2[t]=s;
    }
}

__global__ void final_out_k(const float* __restrict__ h4, const float* __restrict__ fcw2,
                            const float* __restrict__ fcb2, float* __restrict__ out)
{
    int warpId = threadIdx.x >> 5; int lane = threadIdx.x & 31;
    int row = blockIdx.x*8 + warpId;
    const float* hr = h4 + (size_t)row*FF;
    float s0=0.f, s1=0.f;
    #pragma unroll
    for (int f=lane; f<FF; f+=32){
        float h = hr[f];
        s0 = fmaf(h, fcw2[2*f],   s0);
        s1 = fmaf(h, fcw2[2*f+1], s1);
    }
    #pragma unroll
    for (int o=16;o;o>>=1){
        s0 += __shfl_down_sync(0xffffffffu, s0, o);
        s1 += __shfl_down_sync(0xffffffffu, s1, o);
    }
    if (lane==0){ out[(size_t)row*2]=s0+fcb2[0]; out[(size_t)row*2+1]=s1+fcb2[1]; }
}

// ---------------- host ----------------
extern "C" void kernel_launch(void* const* d_in, const int* in_sizes, int n_in,
                              void* d_out, int out_size)
{
    (void)in_sizes; (void)n_in; (void)out_size;
    const float* inputs = (const float*)d_in[0];
    const float* m1w1=(const float*)d_in[3],  *m1b1=(const float*)d_in[4],
               * m1w2=(const float*)d_in[5],  *m1b2=(const float*)d_in[6],
               * m1g =(const float*)d_in[7],  *m1be=(const float*)d_in[8];
    const float* m2w1=(const float*)d_in[9],  *m2b1=(const float*)d_in[10],
               * m2w2=(const float*)d_in[11], *m2b2=(const float*)d_in[12],
               * m2g =(const float*)d_in[13], *m2be=(const float*)d_in[14];
    const float* m3w1=(const float*)d_in[15], *m3b1=(const float*)d_in[16],
               * m3w2=(const float*)d_in[17], *m3b2=(const float*)d_in[18],
               * m3g =(const float*)d_in[19], *m3be=(const float*)d_in[20];
    const float* m4w1=(const float*)d_in[21], *m4b1=(const float*)d_in[22],
               * m4w2=(const float*)d_in[23], *m4b2=(const float*)d_in[24],
               * m4g =(const float*)d_in[25], *m4be=(const float*)d_in[26];
    const float* fcw =(const float*)d_in[27], *fcb =(const float*)d_in[28];
    float* out = (float*)d_out;

    float *nodeA,*nodeB,*nodeC,*nodeD,*P,*Q,*S,*R,*inc,*bigA,*bigB;
    float *psum,*psq,*scale,*shift,*wsk,*db,*fcw2,*fcb2;
    cudaGetSymbolAddress((void**)&nodeA, g_nodeA);
    cudaGetSymbolAddress((void**)&nodeB, g_nodeB);
    cudaGetSymbolAddress((void**)&nodeC, g_nodeC);
    cudaGetSymbolAddress((void**)&nodeD, g_nodeD);
    cudaGetSymbolAddress((void**)&P,     g_P);
    cudaGetSymbolAddress((void**)&Q,     g_Q);
    cudaGetSymbolAddress((void**)&S,     g_S);
    cudaGetSymbolAddress((void**)&R,     g_R);
    cudaGetSymbolAddress((void**)&inc,   g_inc);
    cudaGetSymbolAddress((void**)&bigA,  g_bigA);
    cudaGetSymbolAddress((void**)&bigB,  g_bigB);
    cudaGetSymbolAddress((void**)&psum,  g_psum);
    cudaGetSymbolAddress((void**)&psq,   g_psq);
    cudaGetSymbolAddress((void**)&scale, g_scale);
    cudaGetSymbolAddress((void**)&shift, g_shift);
    cudaGetSymbolAddress((void**)&wsk,   g_wskip);
    cudaGetSymbolAddress((void**)&db,    g_dbias);
    cudaGetSymbolAddress((void**)&fcw2,  g_fcw2);
    cudaGetSymbolAddress((void**)&fcb2,  g_fcb2);

    dim3 gN(NODE_CH, 4), gB(BIG_CH, 4);

    // mlp1 (node level)
    gemm_k<0,false,true,true,false,false><<<gN,64>>>(inputs,0,0, m1w1, m1b1, 0,0, 0,0,0, nodeA, 0,0);
    gemm_k<0,false,true,true,true ,false><<<gN,64>>>(nodeA ,0,0, m1w2, m1b2, 0,0, 0,0,0, nodeB, psum, psq);
    finalize_bn<<<1,256>>>(psum,psq,NODE_CH,m1g,m1be,1.f/NODE_M, scale+0, shift+0);

    // P/Q = BN1(x) @ mlp2_w1 halves (bias b1 folded into P)
    gemm_k<0,true ,true ,false,false,false><<<gN,64>>>(nodeB,0,0, m2w1,       m2b1, scale+0, shift+0, 0,0,0, P, 0,0);
    gemm_k<0,true ,false,false,false,false><<<gN,64>>>(nodeB,0,0, m2w1+65536, 0,    scale+0, shift+0, 0,0,0, Q, 0,0);

    // mlp2 layer2 (big): h2pre = ELU( ELU(P[s]+Q[r]) @ w2 + b2 ), stats2
    gemm_k<1,false,true ,true ,true ,false><<<gB,64>>>(0, P, Q, m2w2, m2b2, 0,0, 0,0,0, bigA, psum, psq);
    finalize_bn<<<1,256>>>(psum,psq,BIG_CH,m2g,m2be,1.f/BIG_M, scale+256, shift+256);

    // fold BN2 into mlp4 skip path
    fold_skip_k<<<256,256>>>(m4w1, scale+256, wsk);
    fold_dbias_k<<<1,256>>>(m4w1, m4b1, shift+256, db);

    // edge2node (BN2 applied analytically)
    edge2node_k<<<2048,256>>>(bigA, scale+256, shift+256, inc);

    // mlp3 (node level)
    gemm_k<0,false,true,true,false,false><<<gN,64>>>(inc  ,0,0, m3w1, m3b1, 0,0, 0,0,0, nodeC, 0,0);
    gemm_k<0,false,true,true,true ,false><<<gN,64>>>(nodeC,0,0, m3w2, m3b2, 0,0, 0,0,0, nodeD, psum, psq);
    finalize_bn<<<1,256>>>(psum,psq,NODE_CH,m3g,m3be,1.f/NODE_M, scale+512, shift+512);

    // S/R = BN3(x3) @ mlp4_w1 first two row-blocks
    gemm_k<0,true,false,false,false,false><<<gN,64>>>(nodeD,0,0, m4w1,       0, scale+512, shift+512, 0,0,0, S, 0,0);
    gemm_k<0,true,false,false,false,false><<<gN,64>>>(nodeD,0,0, m4w1+65536, 0, scale+512, shift+512, 0,0,0, R, 0,0);

    // mlp4 layer1 (big): t = ELU( h2pre @ wsk + S[s] + R[r] + dbias )
    gemm_k<0,false,false,true ,false,true ><<<gB,64>>>(bigA,0,0, wsk, 0, 0,0, S, R, db, bigB, 0,0);
    // mlp4 layer2 (big): h4pre = ELU( t @ w2 + b2 ), stats4
    gemm_k<0,false,true ,true ,true ,false><<<gB,64>>>(bigB,0,0, m4w2, m4b2, 0,0, 0,0,0, bigA, psum, psq);
    finalize_bn<<<1,256>>>(psum,psq,BIG_CH,m4g,m4be,1.f/BIG_M, scale+768, shift+768);

    // fold BN4 into fc, project
    fold_fc_k<<<1,256>>>(fcw, fcb, scale+768, shift+768, fcw2, fcb2);
    final_out_k<<<BIG_M/8,256>>>(bigA, fcw2, fcb2, out);
}

// round 4
// speedup vs baseline: 2.0046x; 2.0046x over previous
#include <cuda_runtime.h>
#include <cuda_bf16.h>
#include <cstdint>
#include <math.h>

#define NN 64
#define BB 32
#define EE 4032
#define FF 256
#define BIG_M  (BB*EE)       // 129024
#define NODE_M (BB*NN)       // 2048
#define BIG_CH (BIG_M/128)   // 1008
#define NODE_CH (NODE_M/64)  // 32

// ---------------- scratch ----------------
__device__ float g_nodeA[NODE_M*FF];
__device__ float g_nodeB[NODE_M*FF];
__device__ float g_nodeC[NODE_M*FF];
__device__ float g_nodeD[NODE_M*FF];
__device__ float g_PQ[NODE_M*2*FF];
__device__ float g_SR[NODE_M*2*FF];
__device__ float g_inc[NODE_M*FF];
__device__ float g_bigA[(size_t)BIG_M*FF];
__device__ float g_bigB[(size_t)BIG_M*FF];
__device__ float g_psum[BIG_CH*FF];
__device__ float g_psq[BIG_CH*FF];
__device__ float g_scale[4*FF];
__device__ float g_shift[4*FF];
__device__ float g_dbias[FF];
__device__ float g_fcw2[2*FF];
__device__ float g_fcb2[2];
__device__ __nv_bfloat16 g_W2hi[FF*FF], g_W2lo[FF*FF];
__device__ __nv_bfloat16 g_W4hi[FF*FF], g_W4lo[FF*FF];
__device__ __nv_bfloat16 g_WShi[FF*FF], g_WSlo[FF*FF];

__device__ __forceinline__ float eluf(float x){ return x > 0.f ? x : expm1f(x); }

__device__ __forceinline__ uint32_t smem_u32(const void* p){
    uint32_t a;
    asm("{ .reg .u64 t; cvta.to.shared.u64 t, %1; cvt.u32.u64 %0, t; }" : "=r"(a) : "l"(p));
    return a;
}

#define LDSM4(r0,r1,r2,r3, addr) \
    asm volatile("ldmatrix.sync.aligned.m8n8.x4.shared.b16 {%0,%1,%2,%3}, [%4];" \
        : "=r"(r0),"=r"(r1),"=r"(r2),"=r"(r3) : "r"(addr))

#define MMA4(d, a0,a1,a2,a3, b0,b1) \
    asm volatile("mma.sync.aligned.m16n8k16.row.col.f32.bf16.bf16.f32 " \
        "{%0,%1,%2,%3},{%4,%5,%6,%7},{%8,%9},{%0,%1,%2,%3};" \
        : "+f"((d)[0]),"+f"((d)[1]),"+f"((d)[2]),"+f"((d)[3]) \
        : "r"(a0),"r"(a1),"r"(a2),"r"(a3),"r"(b0),"r"(b1))

__device__ __forceinline__ uint32_t pk2(float a, float b){
    __nv_bfloat16 ha = __float2bfloat16(a), hb = __float2bfloat16(b);
    return (uint32_t)(*(uint16_t*)&ha) | ((uint32_t)(*(uint16_t*)&hb) << 16);
}

// smem byte offsets (dynamic)
#define OFF_PO     0
#define OFF_QO     512
#define OFF_AHI    1024
#define OFF_ALO    11264
#define OFF_BHI    21504
#define OFF_BLO    31744
#define OFF_STAGE  1024          // reused after MMAs: [128][129] f32
#define OFF_STATS  67072         // [8 warps][256] f32
#define SMEM_DYN   75264

// ============ big HMMA GEMM: C[128 x 128cols@nh] = A[128x256] @ W^T[256x256] ============
// W given transposed+split: Whi/Wlo are [n][k] bf16 (k contiguous).
// MODE 0: A = Adir;               epi: elu(v+bias[col]), stats
// MODE 1: A = elu(PA[po]+PB[qo]); epi: elu(v+bias[col]), stats  (PQ pitch 512)
// MODE 2: A = Adir;               epi: elu(v + Sg[po][col]+Rg[qo][col]+db[col]), no stats
template<int MODE>
__global__ __launch_bounds__(256, 2) void big_gemm(
    const float* __restrict__ Adir, const float* __restrict__ PA, const float* __restrict__ PB,
    const __nv_bfloat16* __restrict__ Whi, const __nv_bfloat16* __restrict__ Wlo,
    const float* __restrict__ bias, const float* __restrict__ Sg, const float* __restrict__ Rg,
    const float* __restrict__ db,
    float* __restrict__ C, float* __restrict__ pSum, float* __restrict__ pSq)
{
    extern __shared__ __align__(1024) char smem[];
    const uint32_t sb = smem_u32(smem);
    const int tid = threadIdx.x, wid = tid >> 5, l = tid & 31;
    const int rowbase = blockIdx.x * 128;
    const int nh = blockIdx.y;            // 0/1: output cols [nh*128, +128)
    int* po = (int*)(smem + OFF_PO);
    int* qo = (int*)(smem + OFF_QO);

    if (MODE != 0 && tid < 128) {
        int gr = rowbase + tid;
        int b = gr / EE; int e = gr - b*EE;
        int snd = e / 63; int jp = e - snd*63; int rcv = jp + (jp >= snd ? 1 : 0);
        po[tid] = (b*NN + snd)*512;
        qo[tid] = (b*NN + rcv)*512;
    }
    __syncthreads();

    // warp tiling: warp_m = wid&3 (m offset 32*), warp_n = wid>>2 (n offset 64*)
    const int m0 = (wid & 3) * 32;
    const int n0w = (wid >> 2) * 64;

    float acc[2][8][4];
    #pragma unroll
    for (int i=0;i<2;i++)
        #pragma unroll
        for (int j=0;j<8;j++)
            #pragma unroll
            for (int q=0;q<4;q++) acc[i][j][q]=0.f;

    // ldmatrix lane address bases
    const uint32_t aHiBase = sb + OFF_AHI + (uint32_t)((m0 + (l & 15)) * 80 + ((l >> 4) << 4));
    const int bro = (l & 7) + ((l >> 4) << 3);
    const uint32_t bHiBase = sb + OFF_BHI + (uint32_t)((n0w + bro) * 80 + ((l & 8) ? 16 : 0));

    const int prow = tid >> 1;                 // A-prep: row 0..127
    const int pko  = (tid & 1) * 16;           // k sub-offset 0/16

    for (int ks = 0; ks < 8; ks++) {
        const int k0 = ks * 32;
        // ---- A tile: 128 rows x 32 k -> hi/lo bf16 smem ----
        {
            float e8a[8], e8b[8];
            if (MODE == 1) {
                const float* pa = PA + po[prow] + k0 + pko;
                const float* pb = PB + qo[prow] + k0 + pko;
                float4 a0 = *(const float4*)pa, a1 = *(const float4*)(pa+4);
                float4 a2 = *(const float4*)(pa+8), a3 = *(const float4*)(pa+12);
                float4 b0 = *(const float4*)pb, b1 = *(const float4*)(pb+4);
                float4 b2 = *(const float4*)(pb+8), b3 = *(const float4*)(pb+12);
                e8a[0]=eluf(a0.x+b0.x); e8a[1]=eluf(a0.y+b0.y); e8a[2]=eluf(a0.z+b0.z); e8a[3]=eluf(a0.w+b0.w);
                e8a[4]=eluf(a1.x+b1.x); e8a[5]=eluf(a1.y+b1.y); e8a[6]=eluf(a1.z+b1.z); e8a[7]=eluf(a1.w+b1.w);
                e8b[0]=eluf(a2.x+b2.x); e8b[1]=eluf(a2.y+b2.y); e8b[2]=eluf(a2.z+b2.z); e8b[3]=eluf(a2.w+b2.w);
                e8b[4]=eluf(a3.x+b3.x); e8b[5]=eluf(a3.y+b3.y); e8b[6]=eluf(a3.z+b3.z); e8b[7]=eluf(a3.w+b3.w);
            } else {
                const float* pa = Adir + (size_t)(rowbase+prow)*FF + k0 + pko;
                float4 a0 = *(const float4*)pa, a1 = *(const float4*)(pa+4);
                float4 a2 = *(const float4*)(pa+8), a3 = *(const float4*)(pa+12);
                e8a[0]=a0.x; e8a[1]=a0.y; e8a[2]=a0.z; e8a[3]=a0.w;
                e8a[4]=a1.x; e8a[5]=a1.y; e8a[6]=a1.z; e8a[7]=a1.w;
                e8b[0]=a2.x; e8b[1]=a2.y; e8b[2]=a2.z; e8b[3]=a2.w;
                e8b[4]=a3.x; e8b[5]=a3.y; e8b[6]=a3.z; e8b[7]=a3.w;
            }
            uint32_t hi[8], lo[8];
            #pragma unroll
            for (int q = 0; q < 4; q++) {
                float x = e8a[2*q], y = e8a[2*q+1];
                __nv_bfloat16 hx = __float2bfloat16(x), hy = __float2bfloat16(y);
                hi[q] = (uint32_t)(*(uint16_t*)&hx) | ((uint32_t)(*(uint16_t*)&hy) << 16);
                lo[q] = pk2(x - __bfloat162float(hx), y - __bfloat162float(hy));
                float x2 = e8b[2*q], y2 = e8b[2*q+1];
                __nv_bfloat16 hx2 = __float2bfloat16(x2), hy2 = __float2bfloat16(y2);
                hi[4+q] = (uint32_t)(*(uint16_t*)&hx2) | ((uint32_t)(*(uint16_t*)&hy2) << 16);
                lo[4+q] = pk2(x2 - __bfloat162float(hx2), y2 - __bfloat162float(hy2));
            }
            char* ah = smem + OFF_AHI + prow*80 + pko*2;
            char* al = smem + OFF_ALO + prow*80 + pko*2;
            *(uint4*)ah       = make_uint4(hi[0],hi[1],hi[2],hi[3]);
            *(uint4*)(ah+16)  = make_uint4(hi[4],hi[5],hi[6],hi[7]);
            *(uint4*)al       = make_uint4(lo[0],lo[1],lo[2],lo[3]);
            *(uint4*)(al+16)  = make_uint4(lo[4],lo[5],lo[6],lo[7]);
        }
        // ---- B tile: 128 n x 32 k (already bf16 hi/lo in gmem) ----
        {
            const size_t go = (size_t)(nh*128 + prow)*FF + k0 + pko;
            uint4 vh0 = *(const uint4*)(Whi + go);
            uint4 vh1 = *(const uint4*)(Whi + go + 8);
            uint4 vl0 = *(const uint4*)(Wlo + go);
            uint4 vl1 = *(const uint4*)(Wlo + go + 8);
            char* bh = smem + OFF_BHI + prow*80 + pko*2;
            char* bl = smem + OFF_BLO + prow*80 + pko*2;
            *(uint4*)bh      = vh0; *(uint4*)(bh+16) = vh1;
            *(uint4*)bl      = vl0; *(uint4*)(bl+16) = vl1;
        }
        __syncthreads();

        // ---- compute: 2 k16 sub-steps ----
        #pragma unroll
        for (int ksub = 0; ksub < 2; ksub++) {
            uint32_t ah[2][4], alr[2][4];
            #pragma unroll
            for (int mt = 0; mt < 2; mt++) {
                uint32_t ad = aHiBase + (uint32_t)(mt*16*80 + ksub*32);
                LDSM4(ah[mt][0],ah[mt][1],ah[mt][2],ah[mt][3], ad);
                LDSM4(alr[mt][0],alr[mt][1],alr[mt][2],alr[mt][3], ad + (OFF_ALO-OFF_AHI));
            }
            #pragma unroll
            for (int nt2 = 0; nt2 < 4; nt2++) {
                uint32_t bd = bHiBase + (uint32_t)(nt2*16*80 + ksub*32);
                uint32_t bh[4], blo[4];
                LDSM4(bh[0],bh[1],bh[2],bh[3], bd);
                LDSM4(blo[0],blo[1],blo[2],blo[3], bd + (OFF_BLO-OFF_BHI));
                #pragma unroll
                for (int mt = 0; mt < 2; mt++) {
                    #pragma unroll
                    for (int t = 0; t < 2; t++) {
                        float* d = acc[mt][nt2*2+t];
                        MMA4(d, ah[mt][0],ah[mt][1],ah[mt][2],ah[mt][3],  bh[t*2], bh[t*2+1]);
                        MMA4(d, ah[mt][0],ah[mt][1],ah[mt][2],ah[mt][3],  blo[t*2], blo[t*2+1]);
                        MMA4(d, alr[mt][0],alr[mt][1],alr[mt][2],alr[mt][3], bh[t*2], bh[t*2+1]);
                    }
                }
            }
        }
        __syncthreads();
    }

    // ---- stage accums to SMEM [128][129] f32 ----
    float* stage = (float*)(smem + OFF_STAGE);
    #pragma unroll
    for (int mt = 0; mt < 2; mt++) {
        #pragma unroll
        for (int nt = 0; nt < 8; nt++) {
            int r = m0 + mt*16 + (l >> 2);
            int c = n0w + nt*8 + (l & 3)*2;
            stage[r*129 + c]       = acc[mt][nt][0];
            stage[r*129 + c + 1]   = acc[mt][nt][1];
            stage[(r+8)*129 + c]   = acc[mt][nt][2];
            stage[(r+8)*129 + c+1] = acc[mt][nt][3];
        }
    }
    __syncthreads();

    // ---- epilogue: warp-per-16-rows, lane = col (coalesced) ----
    float sS[4], sQ2[4];
    #pragma unroll
    for (int g = 0; g < 4; g++){ sS[g]=0.f; sQ2[g]=0.f; }
    for (int rr = 0; rr < 16; rr++) {
        int r = wid*16 + rr;
        float* cp = C + (size_t)(rowbase + r)*FF + nh*128;
        const float* srP = (MODE==2) ? (Sg + po[r] + nh*128) : nullptr;
        const float* srQ = (MODE==2) ? (Rg + qo[r] + nh*128) : nullptr;
        #pragma unroll
        for (int g = 0; g < 4; g++) {
            int c = g*32 + l;
            float f = stage[r*129 + c];
            if (MODE == 2) f += srP[c] + srQ[c] + db[nh*128 + c];
            else           f += bias[nh*128 + c];
            f = eluf(f);
            cp[c] = f;
            if (MODE != 2) { sS[g] += f; sQ2[g] = fmaf(f, f, sQ2[g]); }
        }
    }
    if (MODE != 2) {
        float* xb = (float*)(smem + OFF_STATS);   // [8][256]
        #pragma unroll
        for (int g = 0; g < 4; g++) {
            xb[wid*256 + g*32 + l]       = sS[g];
            xb[wid*256 + 128 + g*32 + l] = sQ2[g];
        }
        __syncthreads();
        if (tid < 128) {
            float s=0.f, q=0.f;
            #pragma unroll
            for (int w = 0; w < 8; w++){ s += xb[w*256 + tid]; q += xb[w*256 + 128 + tid]; }
            pSum[(size_t)blockIdx.x*FF + nh*128 + tid] = s;
            pSq [(size_t)blockIdx.x*FF + nh*128 + tid] = q;
        }
    }
}

// ============ node-level fp32 GEMM (exact), 256 thr, 64x64 tile ============
__global__ __launch_bounds__(256) void node_gemm(
    const float* __restrict__ A,
    const float* __restrict__ W1, const float* __restrict__ W2,
    const float* __restrict__ b1, const float* __restrict__ b2,
    const float* __restrict__ aSc, const float* __restrict__ aSh,
    int do_elu, int ldc,
    float* __restrict__ C, float* __restrict__ pSum, float* __restrict__ pSq)
{
    __shared__ __align__(16) float As[16][68];
    __shared__ __align__(16) float Bs[16][68];
    const int tid = threadIdx.x;
    const int rowbase = blockIdx.x * 64;
    const int n0g = blockIdx.y * 64;
    const float* W  = (n0g < 256) ? (W1 + n0g) : (W2 + (n0g - 256));
    const float* bp = (n0g < 256) ? b1 : b2;
    const int ty = tid >> 4, tx = tid & 15;
    float acc[4][4];
    #pragma unroll
    for (int i=0;i<4;i++)
        #pragma unroll
        for (int j=0;j<4;j++) acc[i][j]=0.f;

    const int arow = tid >> 2, akq = tid & 3;
    const int bkk = tid >> 4, bnq = tid & 15;
    for (int k0 = 0; k0 < FF; k0 += 16) {
        float4 v = *(const float4*)(A + (size_t)(rowbase+arow)*FF + k0 + akq*4);
        if (aSc) {
            const float4 sc = *(const float4*)(aSc + k0 + akq*4);
            const float4 sh = *(const float4*)(aSh + k0 + akq*4);
            v.x = fmaf(sc.x, v.x, sh.x); v.y = fmaf(sc.y, v.y, sh.y);
            v.z = fmaf(sc.z, v.z, sh.z); v.w = fmaf(sc.w, v.w, sh.w);
        }
        As[akq*4+0][arow]=v.x; As[akq*4+1][arow]=v.y;
        As[akq*4+2][arow]=v.z; As[akq*4+3][arow]=v.w;
        *(float4*)&Bs[bkk][bnq*4] = *(const float4*)(W + (size_t)(k0+bkk)*FF + bnq*4);
        __syncthreads();
        #pragma unroll
        for (int k = 0; k < 16; k++) {
            float4 a4 = *(float4*)&As[k][ty*4];
            float4 b4 = *(float4*)&Bs[k][tx*4];
            float a[4]={a4.x,a4.y,a4.z,a4.w}, b[4]={b4.x,b4.y,b4.z,b4.w};
            #pragma unroll
            for (int i=0;i<4;i++)
                #pragma unroll
                for (int j=0;j<4;j++) acc[i][j] = fmaf(a[i], b[j], acc[i][j]);
        }
        __syncthreads();
    }
    #pragma unroll
    for (int i = 0; i < 4; i++) {
        int grow = rowbase + ty*4 + i;
        #pragma unroll
        for (int j = 0; j < 4; j++) {
            float v = acc[i][j];
            if (bp) v += bp[(n0g & 255) + tx*4 + j];
            if (do_elu) v = eluf(v);
            acc[i][j] = v;
        }
        *(float4*)(C + (size_t)grow*ldc + n0g + tx*4) =
            make_float4(acc[i][0], acc[i][1], acc[i][2], acc[i][3]);
    }
    if (pSum) {
        __syncthreads();
        float* sA = &As[0][0];
        float* sB = &Bs[0][0];
        #pragma unroll
        for (int j = 0; j < 4; j++) {
            float s=0.f, q=0.f;
            #pragma unroll
            for (int i=0;i<4;i++){ float v=acc[i][j]; s+=v; q=fmaf(v,v,q); }
            sA[ty*64 + tx*4 + j] = s;
            sB[ty*64 + tx*4 + j] = q;
        }
        __syncthreads();
        if (tid < 64) {
            float s=0.f, q=0.f;
            #pragma unroll
            for (int t = 0; t < 16; t++){ s += sA[t*64+tid]; q += sB[t*64+tid]; }
            pSum[(size_t)blockIdx.x*FF + n0g + tid] = s;
            pSq [(size_t)blockIdx.x*FF + n0g + tid] = q;
        }
    }
}

// ---------------- small kernels ----------------
// grid 8 blocks x 256 thr; block covers 32 cols, 8 partials each
__global__ void finalize_bn(const float* __restrict__ pSum, const float* __restrict__ pSq,
                            int nchunks, const float* __restrict__ g, const float* __restrict__ beta,
                            float invM, float* __restrict__ sc, float* __restrict__ sh)
{
    __shared__ float rs[256], rq[256];
    int lane = threadIdx.x & 31, part = threadIdx.x >> 5;
    int f = blockIdx.x*32 + lane;
    float s=0.f, q=0.f;
    for (int c=part; c<nchunks; c+=8){ s += pSum[(size_t)c*FF+f]; q += pSq[(size_t)c*FF+f]; }
    rs[threadIdx.x]=s; rq[threadIdx.x]=q;
    __syncthreads();
    if (part == 0){
        #pragma unroll
        for (int w=1; w<8; w++){ s += rs[w*32+lane]; q += rq[w*32+lane]; }
        float mean = s*invM;
        float var  = fmaf(-mean, mean, q*invM);
        float a = g[f]*rsqrtf(var + 1e-5f);
        sc[f]=a; sh[f] = fmaf(-mean, a, beta[f]);
    }
}

__global__ void edge2node_k(const float* __restrict__ h2, const float* __restrict__ sc,
                            const float* __restrict__ sh, float* __restrict__ inc)
{
    int bn = blockIdx.x; int b = bn >> 6; int n = bn & 63; int f = threadIdx.x;
    const float* base = h2 + (size_t)b*EE*FF + f;
    float s = 0.f;
    #pragma unroll
    for (int j=0;j<NN;j++){
        if (j==n) continue;
        int e = j*63 + (j < n ? n-1 : n);
        s += base[(size_t)e*FF];
    }
    inc[(size_t)bn*FF+f] = (sc[f]*s + 63.f*sh[f]) * (1.f/64.f);
}

// transpose + bf16 split: dst[n][k] = src[k][n] * kscale[k]; blockDim (32,32)
__global__ void tsplit_k(const float* __restrict__ src, const float* __restrict__ kscale,
                         __nv_bfloat16* __restrict__ dhi, __nv_bfloat16* __restrict__ dlo)
{
    __shared__ float t[32][33];
    int k0 = blockIdx.x*32, n0 = blockIdx.y*32;
    int tx = threadIdx.x, ty = threadIdx.y;
    float w = src[(size_t)(k0+ty)*FF + n0+tx];
    if (kscale) w *= kscale[k0+ty];
    t[ty][tx] = w;
    __syncthreads();
    float v = t[tx][ty];
    __nv_bfloat16 h = __float2bfloat16(v);
    dhi[(size_t)(n0+ty)*FF + k0+tx] = h;
    dlo[(size_t)(n0+ty)*FF + k0+tx] = __float2bfloat16(v - __bfloat162float(h));
}

__global__ void fold_dbias_k(const float* __restrict__ w1, const float* __restrict__ b1,
                             const float* __restrict__ sh2, float* __restrict__ db)
{
    int c = threadIdx.x;
    float s = b1[c];
    for (int f=0; f<FF; f++) s = fmaf(sh2[f], w1[(size_t)(512+f)*FF + c], s);
    db[c]=s;
}

__global__ void fold_fc_k(const float* __restrict__ fcw, const float* __restrict__ fcb,
                          const float* __restrict__ sc, const float* __restrict__ sh,
                          float* __restrict__ fcw2, float* __restrict__ fcb2)
{
    int t = threadIdx.x;
    fcw2[2*t]   = sc[t]*fcw[2*t];
    fcw2[2*t+1] = sc[t]*fcw[2*t+1];
    if (t < 2){
        float s = fcb[t];
        for (int f=0; f<FF; f++) s = fmaf(sh[f], fcw[2*f+t], s);
        fcb2[t]=s;
    }
}

__global__ void final_out_k(const float* __restrict__ h4, const float* __restrict__ fcw2,
                            const float* __restrict__ fcb2, float* __restrict__ out)
{
    int warpId = threadIdx.x >> 5; int lane = threadIdx.x & 31;
    int row = blockIdx.x*8 + warpId;
    const float* hr = h4 + (size_t)row*FF;
    float s0=0.f, s1=0.f;
    #pragma unroll
    for (int f=lane; f<FF; f+=32){
        float h = hr[f];
        s0 = fmaf(h, fcw2[2*f],   s0);
        s1 = fmaf(h, fcw2[2*f+1], s1);
    }
    #pragma unroll
    for (int o=16;o;o>>=1){
        s0 += __shfl_down_sync(0xffffffffu, s0, o);
        s1 += __shfl_down_sync(0xffffffffu, s1, o);
    }
    if (lane==0){ out[(size_t)row*2]=s0+fcb2[0]; out[(size_t)row*2+1]=s1+fcb2[1]; }
}

// ---------------- host ----------------
extern "C" void kernel_launch(void* const* d_in, const int* in_sizes, int n_in,
                              void* d_out, int out_size)
{
    (void)in_sizes; (void)n_in; (void)out_size;
    const float* inputs = (const float*)d_in[0];
    const float* m1w1=(const float*)d_in[3],  *m1b1=(const float*)d_in[4],
               * m1w2=(const float*)d_in[5],  *m1b2=(const float*)d_in[6],
               * m1g =(const float*)d_in[7],  *m1be=(const float*)d_in[8];
    const float* m2w1=(const float*)d_in[9],  *m2b1=(const float*)d_in[10],
               * m2w2=(const float*)d_in[11], *m2b2=(const float*)d_in[12],
               * m2g =(const float*)d_in[13], *m2be=(const float*)d_in[14];
    const float* m3w1=(const float*)d_in[15], *m3b1=(const float*)d_in[16],
               * m3w2=(const float*)d_in[17], *m3b2=(const float*)d_in[18],
               * m3g =(const float*)d_in[19], *m3be=(const float*)d_in[20];
    const float* m4w1=(const float*)d_in[21], *m4b1=(const float*)d_in[22],
               * m4w2=(const float*)d_in[23], *m4b2=(const float*)d_in[24],
               * m4g =(const float*)d_in[25], *m4be=(const float*)d_in[26];
    const float* fcw =(const float*)d_in[27], *fcb =(const float*)d_in[28];
    float* out = (float*)d_out;

    float *nodeA,*nodeB,*nodeC,*nodeD,*PQ,*SR,*inc,*bigA,*bigB;
    float *psum,*psq,*scale,*shift,*db,*fcw2,*fcb2;
    __nv_bfloat16 *W2hi,*W2lo,*W4hi,*W4lo,*WShi,*WSlo;
    cudaGetSymbolAddress((void**)&nodeA, g_nodeA);
    cudaGetSymbolAddress((void**)&nodeB, g_nodeB);
    cudaGetSymbolAddress((void**)&nodeC, g_nodeC);
    cudaGetSymbolAddress((void**)&nodeD, g_nodeD);
    cudaGetSymbolAddress((void**)&PQ,    g_PQ);
    cudaGetSymbolAddress((void**)&SR,    g_SR);
    cudaGetSymbolAddress((void**)&inc,   g_inc);
    cudaGetSymbolAddress((void**)&bigA,  g_bigA);
    cudaGetSymbolAddress((void**)&bigB,  g_bigB);
    cudaGetSymbolAddress((void**)&psum,  g_psum);
    cudaGetSymbolAddress((void**)&psq,   g_psq);
    cudaGetSymbolAddress((void**)&scale, g_scale);
    cudaGetSymbolAddress((void**)&shift, g_shift);
    cudaGetSymbolAddress((void**)&db,    g_dbias);
    cudaGetSymbolAddress((void**)&fcw2,  g_fcw2);
    cudaGetSymbolAddress((void**)&fcb2,  g_fcb2);
    cudaGetSymbolAddress((void**)&W2hi,  g_W2hi);
    cudaGetSymbolAddress((void**)&W2lo,  g_W2lo);
    cudaGetSymbolAddress((void**)&W4hi,  g_W4hi);
    cudaGetSymbolAddress((void**)&W4lo,  g_W4lo);
    cudaGetSymbolAddress((void**)&WShi,  g_WShi);
    cudaGetSymbolAddress((void**)&WSlo,  g_WSlo);

    cudaFuncSetAttribute(big_gemm<0>, cudaFuncAttributeMaxDynamicSharedMemorySize, SMEM_DYN);
    cudaFuncSetAttribute(big_gemm<1>, cudaFuncAttributeMaxDynamicSharedMemorySize, SMEM_DYN);
    cudaFuncSetAttribute(big_gemm<2>, cudaFuncAttributeMaxDynamicSharedMemorySize, SMEM_DYN);

    dim3 tT(32,32), tG(8,8);
    dim3 gN(NODE_CH, 4), gPQ(NODE_CH, 8);
    dim3 gB(BIG_CH, 2);

    // static weight transposes/splits
    tsplit_k<<<tG, tT>>>(m2w2, nullptr, W2hi, W2lo);
    tsplit_k<<<tG, tT>>>(m4w2, nullptr, W4hi, W4lo);

    // mlp1 (node, fp32 exact)
    node_gemm<<<gN,256>>>(inputs, m1w1, 0, m1b1, 0, 0, 0, 1, FF, nodeA, 0, 0);
    node_gemm<<<gN,256>>>(nodeA , m1w2, 0, m1b2, 0, 0, 0, 1, FF, nodeB, psum, psq);
    finalize_bn<<<8,256>>>(psum, psq, NODE_CH, m1g, m1be, 1.f/NODE_M, scale+0, shift+0);

    // PQ[2048][512] = BN1(x) @ [m2w1_top | m2w1_bot]  (b1 folded into P half)
    node_gemm<<<gPQ,256>>>(nodeB, m2w1, m2w1+65536, m2b1, 0, scale+0, shift+0, 0, 512, PQ, 0, 0);

    // big #1: bigA = elu( elu(P[s]+Q[r]) @ W2 + b2 ), stats -> BN2
    big_gemm<1><<<gB,256,SMEM_DYN>>>(0, PQ, PQ+256, W2hi, W2lo, m2b2, 0,0,0, bigA, psum, psq);
    finalize_bn<<<8,256>>>(psum, psq, BIG_CH, m2g, m2be, 1.f/BIG_M, scale+256, shift+256);

    // fold BN2 into skip weight + dbias
    tsplit_k<<<tG, tT>>>(m4w1 + 512*FF, scale+256, WShi, WSlo);
    fold_dbias_k<<<1,256>>>(m4w1, m4b1, shift+256, db);

    // edge2node (BN2 applied analytically)
    edge2node_k<<<2048,256>>>(bigA, scale+256, shift+256, inc);

    // mlp3 (node)
    node_gemm<<<gN,256>>>(inc  , m3w1, 0, m3b1, 0, 0, 0, 1, FF, nodeC, 0, 0);
    node_gemm<<<gN,256>>>(nodeC, m3w2, 0, m3b2, 0, 0, 0, 1, FF, nodeD, psum, psq);
    finalize_bn<<<8,256>>>(psum, psq, NODE_CH, m3g, m3be, 1.f/NODE_M, scale+512, shift+512);

    // SR[2048][512] = BN3(x3) @ [m4w1_s | m4w1_r]  (no bias)
    node_gemm<<<gPQ,256>>>(nodeD, m4w1, m4w1+65536, 0, 0, scale+512, shift+512, 0, 512, SR, 0, 0);

    // big #2: bigB = elu( bigA @ Wskip + S[s] + R[r] + db )
    big_gemm<2><<<gB,256,SMEM_DYN>>>(bigA, 0, 0, WShi, WSlo, 0, SR, SR+256, db, bigB, 0, 0);
    // big #3: bigA = elu( bigB @ W4 + b2 ), stats -> BN4
    big_gemm<0><<<gB,256,SMEM_DYN>>>(bigB, 0, 0, W4hi, W4lo, m4b2, 0,0,0, bigA, psum, psq);
    finalize_bn<<<8,256>>>(psum, psq, BIG_CH, m4g, m4be, 1.f/BIG_M, scale+768, shift+768);

    // fold BN4 into fc; project
    fold_fc_k<<<1,256>>>(fcw, fcb, scale+768, shift+768, fcw2, fcb2);
    final_out_k<<<BIG_M/8,256>>>(bigA, fcw2, fcb2, out);
}